// round 6
// baseline (speedup 1.0000x reference)
#include <cuda_runtime.h>
#include <cuda_fp16.h>
#include <math.h>

#define NN 20000
#define NE 320000
#define NR 200
#define DL 16
#define G  64
#define DW 300
#define DH 256
#define HD 128
#define NC 2000
#define BB 4
#define TT 32
#define G3 (3*HD)    // 384
#define BG (BB*G)    // 256
#define H1 1024
#define FEAT (G+DH)  // 320

// k_gru dyn smem: gx + hs4 + gh + part + msk
#define SMEM_GRU (BB*TT*G3*4 + HD*16 + BB*G3*4 + 384*16 + BB*TT*4)  // 211456

// ---------------- scratch ----------------
__device__ float g_gx[2][BB][TT][G3];
__device__ float g_qemb[BB][DH];
__device__ float g_qg[BB][G];
__device__ __half2 g_nf0h[NN][BG/2];
__device__ float g_sacc[NN][BG];
__device__ float g_nf1[NN][BG];
__device__ int   g_deg[NN];          // statically zero; re-zeroed by k_scan
__device__ int   g_off[NN+1];
__device__ int   g_cur[NN];
__device__ int   g_psrc[NE];
__device__ float g_pw[NE];
__device__ float g_scores[BB][NN];
__device__ unsigned g_bmaxU[BB];     // zeroed by k_logits tail
__device__ float g_agg[BB][G];       // zeroed by k_logits tail
__device__ float g_den[BB];          // zeroed by k_logits tail
__device__ float g_hidp[4][BB][H1];

// ---------------- helpers ----------------
__device__ __forceinline__ unsigned fenc(float f) {
    unsigned u = __float_as_uint(f);
    return (u & 0x80000000u) ? ~u : (u | 0x80000000u);
}
__device__ __forceinline__ float fdec(unsigned e) {
    return (e & 0x80000000u) ? __uint_as_float(e & 0x7FFFFFFFu)
                             : __uint_as_float(~e);
}
__device__ __forceinline__ float sigm(float x) { return 1.f / (1.f + __expf(-x)); }
__device__ __forceinline__ float tanh_fast(float x) { return 2.f / (1.f + __expf(-2.f * x)) - 1.f; }

__device__ __forceinline__ void fma2(unsigned long long& d, unsigned long long a,
                                     unsigned long long b, unsigned long long c) {
    asm("fma.rn.f32x2 %0, %1, %2, %3;" : "=l"(d) : "l"(a), "l"(b), "l"(c));
}
__device__ __forceinline__ void add2(unsigned long long& d, unsigned long long a,
                                     unsigned long long b) {
    asm("add.rn.f32x2 %0, %1, %2;" : "=l"(d) : "l"(a), "l"(b));
}
__device__ __forceinline__ unsigned long long pk2(float x, float y) {
    unsigned long long r; asm("mov.b64 %0, {%1, %2};" : "=l"(r) : "f"(x), "f"(y)); return r;
}
__device__ __forceinline__ float2 upk2(unsigned long long v) {
    float2 f; asm("mov.b64 {%0, %1}, %2;" : "=f"(f.x), "=f"(f.y) : "l"(v)); return f;
}

// ---------------- kernels ----------------

// input gates gx = x @ Wx + bx.  64 blocks x 384 threads
__global__ void k_gx(const int* __restrict__ q, const float* __restrict__ embw,
                     const float* __restrict__ WxF, const float* __restrict__ bxF,
                     const float* __restrict__ WxB, const float* __restrict__ bxB) {
    int d = blockIdx.x >> 5;
    int grp = blockIdx.x & 31;
    const float* Wx = d ? WxB : WxF;
    const float* bx = d ? bxB : bxF;
    __shared__ unsigned long long xs01[DW];
    __shared__ unsigned long long xs23[DW];
    int bt0 = grp * 4;
    int tok0 = q[((bt0 + 0) >> 5) * TT + ((bt0 + 0) & 31)];
    int tok1 = q[((bt0 + 1) >> 5) * TT + ((bt0 + 1) & 31)];
    int tok2 = q[((bt0 + 2) >> 5) * TT + ((bt0 + 2) & 31)];
    int tok3 = q[((bt0 + 3) >> 5) * TT + ((bt0 + 3) & 31)];
    for (int k = threadIdx.x; k < DW; k += blockDim.x) {
        float e0 = embw[tok0 * DW + k];
        float e1 = embw[tok1 * DW + k];
        float e2 = embw[tok2 * DW + k];
        float e3 = embw[tok3 * DW + k];
        xs01[k] = pk2(e0, e1);
        xs23[k] = pk2(e2, e3);
    }
    __syncthreads();
    int j = threadIdx.x;
    float bj = bx[j];
    unsigned long long a01 = pk2(bj, bj), a23 = a01;
    #pragma unroll 4
    for (int k = 0; k < DW; k++) {
        float w = Wx[k * G3 + j];
        unsigned long long wd = pk2(w, w);
        fma2(a01, xs01[k], wd, a01);
        fma2(a23, xs23[k], wd, a23);
    }
    float2 f01 = upk2(a01), f23 = upk2(a23);
    g_gx[d][(bt0 + 0) >> 5][(bt0 + 0) & 31][j] = f01.x;
    g_gx[d][(bt0 + 1) >> 5][(bt0 + 1) & 31][j] = f01.y;
    g_gx[d][(bt0 + 2) >> 5][(bt0 + 2) & 31][j] = f23.x;
    g_gx[d][(bt0 + 3) >> 5][(bt0 + 3) & 31][j] = f23.y;
}

// GRU recurrence. 2 blocks x 768 threads: k-loop split in half across thread
// halves (w[64]/thread in regs), smem partial reduce, gates 1 elem/thread.
__global__ __launch_bounds__(768, 1) void k_gru(const int* __restrict__ q,
                      const float* __restrict__ WhF, const float* __restrict__ bhF,
                      const float* __restrict__ WhB, const float* __restrict__ bhB) {
    extern __shared__ float sm[];
    float* gx_s = sm;                                       // [BB*TT*G3]
    ulonglong2* hs4 = (ulonglong2*)(sm + BB * TT * G3);     // [HD]
    float* gh = (float*)(hs4 + HD);                         // [BB*G3]
    ulonglong2* part = (ulonglong2*)(gh + BB * G3);         // [384]
    int* msk = (int*)(part + 384);                          // [BB*TT]
    int d = blockIdx.x;
    const float* Wh = d ? WhB : WhF;
    const float* bh = d ? bhB : bhF;
    int tid = threadIdx.x;
    int half = (tid >= 384) ? 1 : 0;
    int j = tid - half * 384;
    // stage gx for this direction (49152 floats)
    {
        const float4* src = (const float4*)&g_gx[d][0][0][0];
        float4* dst = (float4*)gx_s;
        #pragma unroll
        for (int i = 0; i < 16; i++) dst[i * 768 + tid] = src[i * 768 + tid];
    }
    if (tid < BB * TT) msk[tid] = (q[tid] != 0);
    if (tid < HD) hs4[tid] = make_ulonglong2(0ull, 0ull);
    int k0 = half * 64;
    float w[64];
    #pragma unroll
    for (int kk = 0; kk < 64; kk++) w[kk] = Wh[(k0 + kk) * G3 + j];
    unsigned long long binit;
    if (half) binit = pk2(0.f, 0.f);
    else { float bj = bh[j]; binit = pk2(bj, bj); }
    __syncthreads();
    for (int s = 0; s < TT; s++) {
        int t = d ? (TT - 1 - s) : s;
        unsigned long long a01 = binit, a23 = binit;
        #pragma unroll
        for (int kk = 0; kk < 64; kk++) {
            unsigned long long wd = pk2(w[kk], w[kk]);
            ulonglong2 hv = hs4[k0 + kk];
            fma2(a01, hv.x, wd, a01);
            fma2(a23, hv.y, wd, a23);
        }
        if (half) part[j] = make_ulonglong2(a01, a23);
        __syncthreads();
        if (!half) {
            ulonglong2 p = part[j];
            add2(a01, a01, p.x);
            add2(a23, a23, p.y);
            float2 f01 = upk2(a01), f23 = upk2(a23);
            gh[0 * G3 + j] = f01.x; gh[1 * G3 + j] = f01.y;
            gh[2 * G3 + j] = f23.x; gh[3 * G3 + j] = f23.y;
        }
        __syncthreads();
        if (tid < BB * HD) {
            int b = tid >> 7, i = tid & 127;
            const float* gx = &gx_s[(b * TT + t) * G3];
            float r = sigm(gx[i] + gh[b * G3 + i]);
            float z = sigm(gx[HD + i] + gh[b * G3 + HD + i]);
            float n = tanh_fast(gx[2 * HD + i] + r * gh[b * G3 + 2 * HD + i]);
            float hold = ((float*)hs4)[i * 4 + b];
            float hn = (1.f - z) * n + z * hold;
            if (msk[b * TT + t]) ((float*)hs4)[i * 4 + b] = hn;
        }
        __syncthreads();
    }
    if (tid < BB * HD) {
        int b = tid >> 7, i = tid & 127;
        g_qemb[b][d * HD + i] = ((float*)hs4)[i * 4 + b];
    }
}

__global__ void k_qg(const float* __restrict__ Whg, const float* __restrict__ bhg) {
    int tid = threadIdx.x;
    int b = tid >> 6, g = tid & 63;
    float acc = bhg[g];
    #pragma unroll 8
    for (int k = 0; k < DH; k++) acc = fmaf(g_qemb[b][k], Whg[k * G + g], acc);
    g_qg[b][g] = acc;
}

// desc attention -> nf0 (half2 out). Warp/node; smem tile; shuffle-light.
#define NFW 8
#define TP 68   // padded tile row (floats)
__global__ void k_nf0(const int* __restrict__ descs, const float* __restrict__ embd) {
    __shared__ float qg_s[BB][G];            // 1KB
    __shared__ float tile[NFW][DL][TP];      // 34.8KB
    __shared__ float attnw[NFW][DL][BB];     // 2KB
    int tid = threadIdx.x, lane = tid & 31, wl = tid >> 5;
    for (int i = tid; i < BB * G; i += 256) ((float*)qg_s)[i] = ((const float*)g_qg)[i];
    __syncthreads();
    int n = blockIdx.x * NFW + wl;
    if (n >= NN) return;
    // stage 16x64 desc tile
    int tok_l = descs[n * DL + (lane & 15)];
    #pragma unroll
    for (int t = 0; t < DL; t++) {
        int tok = __shfl_sync(0xFFFFFFFFu, tok_l, t);
        float2 e = *(const float2*)&embd[tok * G + 2 * lane];
        *(float2*)&tile[wl][t][2 * lane] = e;
    }
    __syncwarp();
    // scores: lane -> b = lane>>3, tokens t0=(lane&7)*2, t1=t0+1
    int b = lane >> 3, t0 = (lane & 7) * 2, t1 = t0 + 1;
    float s0 = 0.f, s1 = 0.f;
    #pragma unroll
    for (int g4 = 0; g4 < G; g4 += 4) {
        float4 qv = *(float4*)&qg_s[b][g4];
        float4 x0 = *(float4*)&tile[wl][t0][g4];
        float4 x1 = *(float4*)&tile[wl][t1][g4];
        s0 += qv.x * x0.x + qv.y * x0.y + qv.z * x0.z + qv.w * x0.w;
        s1 += qv.x * x1.x + qv.y * x1.y + qv.z * x1.z + qv.w * x1.w;
    }
    // softmax over 16 tokens within the 8-lane b-group
    float m = fmaxf(s0, s1);
    m = fmaxf(m, __shfl_xor_sync(0xFFFFFFFFu, m, 1));
    m = fmaxf(m, __shfl_xor_sync(0xFFFFFFFFu, m, 2));
    m = fmaxf(m, __shfl_xor_sync(0xFFFFFFFFu, m, 4));
    float e0 = __expf(s0 - m), e1 = __expf(s1 - m);
    float den = e0 + e1;
    den += __shfl_xor_sync(0xFFFFFFFFu, den, 1);
    den += __shfl_xor_sync(0xFFFFFFFFu, den, 2);
    den += __shfl_xor_sync(0xFFFFFFFFu, den, 4);
    float inv = 1.f / den;
    attnw[wl][t0][b] = e0 * inv;
    attnw[wl][t1][b] = e1 * inv;
    __syncwarp();
    // weighted sum: lane owns g pair (2*lane, 2*lane+1), all 4 batches
    float o00 = 0.f, o01 = 0.f, o10 = 0.f, o11 = 0.f;
    float o20 = 0.f, o21 = 0.f, o30 = 0.f, o31 = 0.f;
    #pragma unroll
    for (int t = 0; t < DL; t++) {
        float2 x = *(float2*)&tile[wl][t][2 * lane];
        float4 w4 = *(float4*)&attnw[wl][t][0];
        o00 = fmaf(w4.x, x.x, o00); o01 = fmaf(w4.x, x.y, o01);
        o10 = fmaf(w4.y, x.x, o10); o11 = fmaf(w4.y, x.y, o11);
        o20 = fmaf(w4.z, x.x, o20); o21 = fmaf(w4.z, x.y, o21);
        o30 = fmaf(w4.w, x.x, o30); o31 = fmaf(w4.w, x.y, o31);
    }
    g_nf0h[n][0 * 32 + lane] = __floats2half2_rn(o00, o01);
    g_nf0h[n][1 * 32 + lane] = __floats2half2_rn(o10, o11);
    g_nf0h[n][2 * 32 + lane] = __floats2half2_rn(o20, o21);
    g_nf0h[n][3 * 32 + lane] = __floats2half2_rn(o30, o31);
}

__global__ void k_deg(const int* __restrict__ dst) {
    int e = blockIdx.x * blockDim.x + threadIdx.x;
    if (e < NE) atomicAdd(&g_deg[dst[e]], 1);
}

// single-block warp-shfl exclusive scan; re-zeroes g_deg for next replay
__global__ void k_scan() {
    __shared__ int wsum[32];
    __shared__ int carry;
    int tid = threadIdx.x, lane = tid & 31, wid = tid >> 5;
    if (tid == 0) carry = 0;
    __syncthreads();
    for (int base = 0; base < NN; base += 1024) {
        int idx = base + tid;
        int v = (idx < NN) ? g_deg[idx] : 0;
        if (idx < NN) g_deg[idx] = 0;
        int x = v;
        #pragma unroll
        for (int o = 1; o < 32; o <<= 1) {
            int y = __shfl_up_sync(0xFFFFFFFFu, x, o);
            if (lane >= o) x += y;
        }
        if (lane == 31) wsum[wid] = x;
        __syncthreads();
        if (wid == 0) {
            int s = wsum[lane];
            #pragma unroll
            for (int o = 1; o < 32; o <<= 1) {
                int y = __shfl_up_sync(0xFFFFFFFFu, s, o);
                if (lane >= o) s += y;
            }
            wsum[lane] = s;
        }
        __syncthreads();
        int ex = carry + (wid ? wsum[wid - 1] : 0) + x - v;
        if (idx < NN) { g_off[idx] = ex; g_cur[idx] = ex; }
        __syncthreads();
        if (tid == 0) carry += wsum[31];
        __syncthreads();
    }
    if (tid == 0) g_off[NN] = carry;
}

__global__ void k_perm(const int* __restrict__ src, const int* __restrict__ dst,
                       const int* __restrict__ et, const float* __restrict__ wcomp) {
    int e = blockIdx.x * blockDim.x + threadIdx.x;
    if (e >= NE) return;
    int pos = atomicAdd(&g_cur[dst[e]], 1);
    g_psrc[pos] = src[e];
    g_pw[pos]   = wcomp[et[e]];
}

// edge aggregation over half payloads, fp32 accumulate; one warp per dst node
__global__ void k_agg() {
    int warp = (blockIdx.x * blockDim.x + threadIdx.x) >> 5;
    int lane = threadIdx.x & 31;
    if (warp >= NN) return;
    int n = warp;
    int beg = g_off[n], end = g_off[n + 1];
    float a[8] = {0, 0, 0, 0, 0, 0, 0, 0};
    for (int i = beg; i < end; i++) {
        int s = g_psrc[i];
        float w = g_pw[i];
        uint4 v = *(const uint4*)&g_nf0h[s][lane * 4];
        const __half2* hp = (const __half2*)&v;
        #pragma unroll
        for (int qq = 0; qq < 4; qq++) {
            float2 f = __half22float2(hp[qq]);
            a[2 * qq]     = fmaf(w, f.x, a[2 * qq]);
            a[2 * qq + 1] = fmaf(w, f.y, a[2 * qq + 1]);
        }
    }
    float4* op = (float4*)&g_sacc[n][lane * 8];
    op[0] = make_float4(a[0], a[1], a[2], a[3]);
    op[1] = make_float4(a[4], a[5], a[6], a[7]);
}

// nf1 = relu(s @ bases + bias), fused pooling scores + per-block running max
__global__ void k_rgcn(const float* __restrict__ bases, const float* __restrict__ bias) {
    __shared__ float bs[G * G];
    __shared__ float srow[BG];
    __shared__ float swred[8];
    int tid = threadIdx.x;   // 256
    for (int i = tid; i < G * G; i += 256) bs[i] = bases[i];
    int b = tid >> 6, g = tid & 63;
    float bia = bias[g];
    float qv = g_qg[b][g];
    float mloc = -3.0e38f;
    __syncthreads();
    for (int n = blockIdx.x; n < NN; n += gridDim.x) {
        srow[tid] = g_sacc[n][tid];
        __syncthreads();
        float acc = bia;
        const float* sb = &srow[b * G];
        #pragma unroll 8
        for (int k = 0; k < G; k++) acc = fmaf(sb[k], bs[k * G + g], acc);
        acc = fmaxf(acc, 0.f);
        g_nf1[n][tid] = acc;
        float p = acc * qv;
        p += __shfl_xor_sync(0xFFFFFFFFu, p, 16);
        p += __shfl_xor_sync(0xFFFFFFFFu, p, 8);
        p += __shfl_xor_sync(0xFFFFFFFFu, p, 4);
        p += __shfl_xor_sync(0xFFFFFFFFu, p, 2);
        p += __shfl_xor_sync(0xFFFFFFFFu, p, 1);
        if ((tid & 31) == 0) swred[tid >> 5] = p;
        __syncthreads();
        if (tid < BB) {
            float sv = swred[2 * tid] + swred[2 * tid + 1];
            g_scores[tid][n] = sv;
            mloc = fmaxf(mloc, sv);
        }
        __syncthreads();
    }
    if (tid < BB) atomicMax(&g_bmaxU[tid], fenc(mloc));
}

__global__ void k_sum() {
    int tid = threadIdx.x;   // 256: (b,g)
    int b = tid >> 6, g = tid & 63;
    float m = fdec(g_bmaxU[b]);
    float acc = 0.f, den = 0.f;
    for (int n = blockIdx.x; n < NN; n += gridDim.x) {
        float e = __expf(g_scores[b][n] - m);
        acc = fmaf(e, g_nf1[n][tid], acc);
        if (g == 0) den += e;
    }
    atomicAdd(&g_agg[b][g], acc);
    if (g == 0) atomicAdd(&g_den[b], den);
}

// hidden partials: 32 blocks = (hblk 0..7) x (kp 0..3); 128 threads
__global__ void k_hidden(const float* __restrict__ W1) {
    int hb = blockIdx.x >> 2, kp = blockIdx.x & 3;
    int tid = threadIdx.x;
    int h = hb * 128 + tid;
    int k0 = kp * 80;
    __shared__ float feat[BB][80];
    for (int i = tid; i < BB * 80; i += 128) {
        int b = i / 80, kk = i % 80, k = k0 + kk;
        feat[b][kk] = (k < G) ? (g_agg[b][k] / g_den[b]) : g_qemb[b][k - G];
    }
    __syncthreads();
    float a0 = 0.f, a1 = 0.f, a2 = 0.f, a3 = 0.f;
    #pragma unroll 4
    for (int kk = 0; kk < 80; kk++) {
        float w = W1[(k0 + kk) * H1 + h];
        a0 = fmaf(feat[0][kk], w, a0);
        a1 = fmaf(feat[1][kk], w, a1);
        a2 = fmaf(feat[2][kk], w, a2);
        a3 = fmaf(feat[3][kk], w, a3);
    }
    g_hidp[kp][0][h] = a0; g_hidp[kp][1][h] = a1;
    g_hidp[kp][2][h] = a2; g_hidp[kp][3][h] = a3;
}

// logits: 63 blocks x 256 (8 k-parts x 32 classes); relu+bias fused;
// block 0 re-zeroes accumulators for the next replay.
__global__ void k_logits(const float* __restrict__ W2, const float* __restrict__ b1,
                         const float* __restrict__ b2, float* __restrict__ out) {
    __shared__ float hsm[BB][H1];
    __shared__ float red[8][32][BB];
    int tid = threadIdx.x;
    for (int i = tid; i < BB * H1; i += 256) {
        int b = i >> 10, k = i & (H1 - 1);
        float v = g_hidp[0][b][k] + g_hidp[1][b][k] + g_hidp[2][b][k] + g_hidp[3][b][k] + b1[k];
        hsm[b][k] = fmaxf(v, 0.f);
    }
    __syncthreads();
    int kp = tid >> 5, cl = tid & 31;
    int c = blockIdx.x * 32 + cl;
    float a0 = 0.f, a1 = 0.f, a2 = 0.f, a3 = 0.f;
    if (c < NC) {
        int k0 = kp * 128;
        #pragma unroll 4
        for (int k = k0; k < k0 + 128; k++) {
            float w = W2[k * NC + c];
            a0 = fmaf(hsm[0][k], w, a0);
            a1 = fmaf(hsm[1][k], w, a1);
            a2 = fmaf(hsm[2][k], w, a2);
            a3 = fmaf(hsm[3][k], w, a3);
        }
    }
    red[kp][cl][0] = a0; red[kp][cl][1] = a1; red[kp][cl][2] = a2; red[kp][cl][3] = a3;
    __syncthreads();
    if (kp == 0 && c < NC) {
        float bb2 = b2[c];
        #pragma unroll
        for (int b = 0; b < BB; b++) {
            float s = bb2;
            #pragma unroll
            for (int p = 0; p < 8; p++) s += red[p][cl][b];
            out[b * NC + c] = s;
        }
    }
    if (blockIdx.x == 0) {
        if (tid < BB * G) ((float*)g_agg)[tid] = 0.f;
        if (tid < BB) { g_den[tid] = 0.f; g_bmaxU[tid] = 0u; }
    }
}

// ---------------- launch ----------------
extern "C" void kernel_launch(void* const* d_in, const int* in_sizes, int n_in,
                              void* d_out, int out_size) {
    const int*   questions = (const int*)d_in[0];
    const int*   node_descs= (const int*)d_in[1];
    const int*   edge_src  = (const int*)d_in[2];
    const int*   edge_dst  = (const int*)d_in[3];
    const int*   edge_type = (const int*)d_in[4];
    const float* emb_word  = (const float*)d_in[5];
    const float* emb_desc  = (const float*)d_in[6];
    const float* Wx_f = (const float*)d_in[7];
    const float* Wh_f = (const float*)d_in[8];
    const float* bx_f = (const float*)d_in[9];
    const float* bh_f = (const float*)d_in[10];
    const float* Wx_b = (const float*)d_in[11];
    const float* Wh_b = (const float*)d_in[12];
    const float* bx_b = (const float*)d_in[13];
    const float* bh_b = (const float*)d_in[14];
    const float* W_hg = (const float*)d_in[15];
    const float* b_hg = (const float*)d_in[16];
    const float* bases = (const float*)d_in[17];
    const float* w_comp = (const float*)d_in[18];
    const float* rgcn_bias = (const float*)d_in[19];
    const float* W1 = (const float*)d_in[20];
    const float* b1 = (const float*)d_in[21];
    const float* W2 = (const float*)d_in[22];
    const float* b2 = (const float*)d_in[23];
    float* out = (float*)d_out;

    static cudaStream_t s1 = nullptr;
    static cudaEvent_t ev0 = nullptr, ev1 = nullptr;
    if (!s1) {
        cudaStreamCreateWithFlags(&s1, cudaStreamNonBlocking);
        cudaEventCreateWithFlags(&ev0, cudaEventDisableTiming);
        cudaEventCreateWithFlags(&ev1, cudaEventDisableTiming);
        cudaFuncSetAttribute(k_gru, cudaFuncAttributeMaxDynamicSharedMemorySize, SMEM_GRU);
    }

    cudaEventRecord(ev0, 0);
    cudaStreamWaitEvent(s1, ev0, 0);

    k_gx<<<64, G3>>>(questions, emb_word, Wx_f, bx_f, Wx_b, bx_b);       // 1
    k_deg<<<(NE + 255) / 256, 256, 0, s1>>>(edge_dst);                    // 2
    k_scan<<<1, 1024, 0, s1>>>();                                         // 3
    k_gru<<<2, 768, SMEM_GRU>>>(questions, Wh_f, bh_f, Wh_b, bh_b);      // 4 (ncu slot)
    k_perm<<<(NE + 255) / 256, 256, 0, s1>>>(edge_src, edge_dst, edge_type, w_comp); // 5
    cudaEventRecord(ev1, s1);
    k_qg<<<1, 256>>>(W_hg, b_hg);                                         // 6
    k_nf0<<<NN / NFW, 256>>>(node_descs, emb_desc);                       // 7
    cudaStreamWaitEvent(0, ev1, 0);
    k_agg<<<(NN * 32 + 255) / 256, 256>>>();                              // 8
    k_rgcn<<<1250, 256>>>(bases, rgcn_bias);                              // 9
    k_sum<<<256, 256>>>();                                                // 10
    k_hidden<<<32, 128>>>(W1);                                            // 11
    k_logits<<<63, 256>>>(W2, b1, b2, out);                               // 12
}

// round 9
// speedup vs baseline: 1.4830x; 1.4830x over previous
#include <cuda_runtime.h>
#include <cuda_fp16.h>
#include <math.h>

#define NN 20000
#define NE 320000
#define NR 200
#define DL 16
#define G  64
#define DW 300
#define DH 256
#define HD 128
#define NC 2000
#define BB 4
#define TT 32
#define G3 (3*HD)    // 384
#define BG (BB*G)    // 256
#define H1 1024
#define FEAT (G+DH)  // 320
#define RB 296       // rgcn blocks

// k_gru dyn smem: gx + hs4 + gh + msk
#define SMEM_GRU (BB*TT*G3*4 + HD*16 + BB*G3*4 + BB*TT*4)   // 205312

// ---------------- scratch ----------------
__device__ float g_gx[2][BB][TT][G3];
__device__ float g_qemb[BB][DH];
__device__ float g_qg[BB][G];
__device__ __half2 g_nf0h[NN][BG/2];
__device__ float g_sacc[NN][BG];
__device__ int   g_deg[NN];          // statically zero; re-zeroed by k_scan
__device__ int   g_off[NN+1];
__device__ int   g_cur[NN];
__device__ int   g_psrc[NE];
__device__ float g_pw[NE];
__device__ float g_pm[RB][BB];       // per-block softmax max
__device__ float g_pden[RB][BB];     // per-block softmax denom
__device__ float g_pagg[RB][BB][G];  // per-block weighted agg
__device__ float g_pool[BB][G];      // final pooled node feature
__device__ float g_hidp[4][BB][H1];

// ---------------- helpers ----------------
__device__ __forceinline__ float sigm(float x) { return 1.f / (1.f + __expf(-x)); }
__device__ __forceinline__ float tanh_fast(float x) { return 2.f / (1.f + __expf(-2.f * x)) - 1.f; }

__device__ __forceinline__ void fma2(unsigned long long& d, unsigned long long a,
                                     unsigned long long b, unsigned long long c) {
    asm("fma.rn.f32x2 %0, %1, %2, %3;" : "=l"(d) : "l"(a), "l"(b), "l"(c));
}
__device__ __forceinline__ unsigned long long pk2(float x, float y) {
    unsigned long long r; asm("mov.b64 %0, {%1, %2};" : "=l"(r) : "f"(x), "f"(y)); return r;
}
__device__ __forceinline__ float2 upk2(unsigned long long v) {
    float2 f; asm("mov.b64 {%0, %1}, %2;" : "=f"(f.x), "=f"(f.y) : "l"(v)); return f;
}

// ---------------- kernels ----------------

// input gates gx = x @ Wx + bx.  64 blocks x 384 threads
__global__ void k_gx(const int* __restrict__ q, const float* __restrict__ embw,
                     const float* __restrict__ WxF, const float* __restrict__ bxF,
                     const float* __restrict__ WxB, const float* __restrict__ bxB) {
    int d = blockIdx.x >> 5;
    int grp = blockIdx.x & 31;
    const float* Wx = d ? WxB : WxF;
    const float* bx = d ? bxB : bxF;
    __shared__ unsigned long long xs01[DW];
    __shared__ unsigned long long xs23[DW];
    int bt0 = grp * 4;
    int tok0 = q[((bt0 + 0) >> 5) * TT + ((bt0 + 0) & 31)];
    int tok1 = q[((bt0 + 1) >> 5) * TT + ((bt0 + 1) & 31)];
    int tok2 = q[((bt0 + 2) >> 5) * TT + ((bt0 + 2) & 31)];
    int tok3 = q[((bt0 + 3) >> 5) * TT + ((bt0 + 3) & 31)];
    for (int k = threadIdx.x; k < DW; k += blockDim.x) {
        float e0 = embw[tok0 * DW + k];
        float e1 = embw[tok1 * DW + k];
        float e2 = embw[tok2 * DW + k];
        float e3 = embw[tok3 * DW + k];
        xs01[k] = pk2(e0, e1);
        xs23[k] = pk2(e2, e3);
    }
    __syncthreads();
    int j = threadIdx.x;
    float bj = bx[j];
    unsigned long long a01 = pk2(bj, bj), a23 = a01;
    #pragma unroll 4
    for (int k = 0; k < DW; k++) {
        float w = Wx[k * G3 + j];
        unsigned long long wd = pk2(w, w);
        fma2(a01, xs01[k], wd, a01);
        fma2(a23, xs23[k], wd, a23);
    }
    float2 f01 = upk2(a01), f23 = upk2(a23);
    g_gx[d][(bt0 + 0) >> 5][(bt0 + 0) & 31][j] = f01.x;
    g_gx[d][(bt0 + 1) >> 5][(bt0 + 1) & 31][j] = f01.y;
    g_gx[d][(bt0 + 2) >> 5][(bt0 + 2) & 31][j] = f23.x;
    g_gx[d][(bt0 + 3) >> 5][(bt0 + 3) & 31][j] = f23.y;
}

// GRU recurrence (r5 version — best measured). 2 blocks x 384 threads;
// Wh register-resident; gx + masks in smem. NOTE: gate phase MUST loop
// u = tid, tid+384 to cover all BB*HD = 512 (b,i) pairs with 384 threads.
__global__ __launch_bounds__(G3, 1) void k_gru(const int* __restrict__ q,
                      const float* __restrict__ WhF, const float* __restrict__ bhF,
                      const float* __restrict__ WhB, const float* __restrict__ bhB) {
    extern __shared__ float sm[];
    float* gx_s = sm;                                       // [BB*TT*G3]
    ulonglong2* hs4 = (ulonglong2*)(sm + BB * TT * G3);     // [HD]
    float* gh = (float*)(hs4 + HD);                         // [BB*G3]
    int* msk = (int*)(gh + BB * G3);                        // [BB*TT]
    int d = blockIdx.x;
    const float* Wh = d ? WhB : WhF;
    const float* bh = d ? bhB : bhF;
    int tid = threadIdx.x;
    {
        const float4* src = (const float4*)&g_gx[d][0][0][0];
        float4* dst = (float4*)gx_s;
        #pragma unroll
        for (int i = 0; i < 32; i++) dst[i * G3 + tid] = src[i * G3 + tid];
    }
    if (tid < BB * TT) msk[tid] = (q[tid] != 0);
    if (tid < HD) hs4[tid] = make_ulonglong2(0ull, 0ull);
    float w[HD];
    #pragma unroll
    for (int k = 0; k < HD; k++) w[k] = Wh[k * G3 + tid];
    float bj = bh[tid];
    unsigned long long bj2 = pk2(bj, bj);
    __syncthreads();
    for (int s = 0; s < TT; s++) {
        int t = d ? (TT - 1 - s) : s;
        unsigned long long a01 = bj2, a23 = bj2;
        #pragma unroll
        for (int k = 0; k < HD; k++) {
            unsigned long long wd = pk2(w[k], w[k]);
            ulonglong2 hv = hs4[k];
            fma2(a01, hv.x, wd, a01);
            fma2(a23, hv.y, wd, a23);
        }
        float2 f01 = upk2(a01), f23 = upk2(a23);
        gh[0 * G3 + tid] = f01.x; gh[1 * G3 + tid] = f01.y;
        gh[2 * G3 + tid] = f23.x; gh[3 * G3 + tid] = f23.y;
        __syncthreads();
        for (int u = tid; u < BB * HD; u += G3) {
            int b = u >> 7, i = u & 127;
            const float* gx = &gx_s[(b * TT + t) * G3];
            float r = sigm(gx[i] + gh[b * G3 + i]);
            float z = sigm(gx[HD + i] + gh[b * G3 + HD + i]);
            float n = tanh_fast(gx[2 * HD + i] + r * gh[b * G3 + 2 * HD + i]);
            float hold = ((float*)hs4)[i * 4 + b];
            float hn = (1.f - z) * n + z * hold;
            if (msk[b * TT + t]) ((float*)hs4)[i * 4 + b] = hn;
        }
        __syncthreads();
    }
    for (int u = tid; u < BB * HD; u += G3) {
        int b = u >> 7, i = u & 127;
        g_qemb[b][d * HD + i] = ((float*)hs4)[i * 4 + b];
    }
}

__global__ void k_qg(const float* __restrict__ Whg, const float* __restrict__ bhg) {
    int tid = threadIdx.x;
    int b = tid >> 6, g = tid & 63;
    float acc = bhg[g];
    #pragma unroll 8
    for (int k = 0; k < DH; k++) acc = fmaf(g_qemb[b][k], Whg[k * G + g], acc);
    g_qg[b][g] = acc;
}

// desc attention -> nf0 (half2 out). Warp/node; smem tile; shuffle-light.
#define NFW 8
#define TP 68   // padded tile row (floats)
__global__ void k_nf0(const int* __restrict__ descs, const float* __restrict__ embd) {
    __shared__ float qg_s[BB][G];
    __shared__ float tile[NFW][DL][TP];
    __shared__ float attnw[NFW][DL][BB];
    int tid = threadIdx.x, lane = tid & 31, wl = tid >> 5;
    for (int i = tid; i < BB * G; i += 256) ((float*)qg_s)[i] = ((const float*)g_qg)[i];
    __syncthreads();
    int n = blockIdx.x * NFW + wl;
    if (n >= NN) return;
    int tok_l = descs[n * DL + (lane & 15)];
    #pragma unroll
    for (int t = 0; t < DL; t++) {
        int tok = __shfl_sync(0xFFFFFFFFu, tok_l, t);
        float2 e = *(const float2*)&embd[tok * G + 2 * lane];
        *(float2*)&tile[wl][t][2 * lane] = e;
    }
    __syncwarp();
    int b = lane >> 3, t0 = (lane & 7) * 2, t1 = t0 + 1;
    float s0 = 0.f, s1 = 0.f;
    #pragma unroll
    for (int g4 = 0; g4 < G; g4 += 4) {
        float4 qv = *(float4*)&qg_s[b][g4];
        float4 x0 = *(float4*)&tile[wl][t0][g4];
        float4 x1 = *(float4*)&tile[wl][t1][g4];
        s0 += qv.x * x0.x + qv.y * x0.y + qv.z * x0.z + qv.w * x0.w;
        s1 += qv.x * x1.x + qv.y * x1.y + qv.z * x1.z + qv.w * x1.w;
    }
    float m = fmaxf(s0, s1);
    m = fmaxf(m, __shfl_xor_sync(0xFFFFFFFFu, m, 1));
    m = fmaxf(m, __shfl_xor_sync(0xFFFFFFFFu, m, 2));
    m = fmaxf(m, __shfl_xor_sync(0xFFFFFFFFu, m, 4));
    float e0 = __expf(s0 - m), e1 = __expf(s1 - m);
    float den = e0 + e1;
    den += __shfl_xor_sync(0xFFFFFFFFu, den, 1);
    den += __shfl_xor_sync(0xFFFFFFFFu, den, 2);
    den += __shfl_xor_sync(0xFFFFFFFFu, den, 4);
    float inv = 1.f / den;
    attnw[wl][t0][b] = e0 * inv;
    attnw[wl][t1][b] = e1 * inv;
    __syncwarp();
    float o00 = 0.f, o01 = 0.f, o10 = 0.f, o11 = 0.f;
    float o20 = 0.f, o21 = 0.f, o30 = 0.f, o31 = 0.f;
    #pragma unroll
    for (int t = 0; t < DL; t++) {
        float2 x = *(float2*)&tile[wl][t][2 * lane];
        float4 w4 = *(float4*)&attnw[wl][t][0];
        o00 = fmaf(w4.x, x.x, o00); o01 = fmaf(w4.x, x.y, o01);
        o10 = fmaf(w4.y, x.x, o10); o11 = fmaf(w4.y, x.y, o11);
        o20 = fmaf(w4.z, x.x, o20); o21 = fmaf(w4.z, x.y, o21);
        o30 = fmaf(w4.w, x.x, o30); o31 = fmaf(w4.w, x.y, o31);
    }
    g_nf0h[n][0 * 32 + lane] = __floats2half2_rn(o00, o01);
    g_nf0h[n][1 * 32 + lane] = __floats2half2_rn(o10, o11);
    g_nf0h[n][2 * 32 + lane] = __floats2half2_rn(o20, o21);
    g_nf0h[n][3 * 32 + lane] = __floats2half2_rn(o30, o31);
}

__global__ void k_deg(const int* __restrict__ dst) {
    int e = blockIdx.x * blockDim.x + threadIdx.x;
    if (e < NE) atomicAdd(&g_deg[dst[e]], 1);
}

// single-block warp-shfl exclusive scan; re-zeroes g_deg for next replay
__global__ void k_scan() {
    __shared__ int wsum[32];
    __shared__ int carry;
    int tid = threadIdx.x, lane = tid & 31, wid = tid >> 5;
    if (tid == 0) carry = 0;
    __syncthreads();
    for (int base = 0; base < NN; base += 1024) {
        int idx = base + tid;
        int v = (idx < NN) ? g_deg[idx] : 0;
        if (idx < NN) g_deg[idx] = 0;
        int x = v;
        #pragma unroll
        for (int o = 1; o < 32; o <<= 1) {
            int y = __shfl_up_sync(0xFFFFFFFFu, x, o);
            if (lane >= o) x += y;
        }
        if (lane == 31) wsum[wid] = x;
        __syncthreads();
        if (wid == 0) {
            int s = wsum[lane];
            #pragma unroll
            for (int o = 1; o < 32; o <<= 1) {
                int y = __shfl_up_sync(0xFFFFFFFFu, s, o);
                if (lane >= o) s += y;
            }
            wsum[lane] = s;
        }
        __syncthreads();
        int ex = carry + (wid ? wsum[wid - 1] : 0) + x - v;
        if (idx < NN) { g_off[idx] = ex; g_cur[idx] = ex; }
        __syncthreads();
        if (tid == 0) carry += wsum[31];
        __syncthreads();
    }
    if (tid == 0) g_off[NN] = carry;
}

__global__ void k_perm(const int* __restrict__ src, const int* __restrict__ dst,
                       const int* __restrict__ et, const float* __restrict__ wcomp) {
    int e = blockIdx.x * blockDim.x + threadIdx.x;
    if (e >= NE) return;
    int pos = atomicAdd(&g_cur[dst[e]], 1);
    g_psrc[pos] = src[e];
    g_pw[pos]   = wcomp[et[e]];
}

// edge aggregation: 2 warps per dst node (warp owns a batch pair); lane owns 8B.
__global__ void k_agg() {
    int gw = (blockIdx.x * blockDim.x + threadIdx.x) >> 5;
    int lane = threadIdx.x & 31;
    if (gw >= NN * 2) return;
    int n = gw >> 1, hb = gw & 1;
    int beg = g_off[n], end = g_off[n + 1];
    float a0 = 0.f, a1 = 0.f, a2 = 0.f, a3 = 0.f;
    int poff = hb * 64 + lane * 2;
    for (int i = beg; i < end; i++) {
        int s = g_psrc[i];
        float w = g_pw[i];
        uint2 v = *(const uint2*)&g_nf0h[s][poff];
        __half2 h0 = *(__half2*)&v.x, h1 = *(__half2*)&v.y;
        float2 f0 = __half22float2(h0), f1 = __half22float2(h1);
        a0 = fmaf(w, f0.x, a0); a1 = fmaf(w, f0.y, a1);
        a2 = fmaf(w, f1.x, a2); a3 = fmaf(w, f1.y, a3);
    }
    *(float4*)&g_sacc[n][hb * 128 + lane * 4] = make_float4(a0, a1, a2, a3);
}

// nf1 = relu(s @ bases + bias) fused with ONLINE-SOFTMAX attention pooling.
// RB blocks; per-block running (m, den, agg); partials combined by k_comb.
__global__ void k_rgcn(const float* __restrict__ bases, const float* __restrict__ bias) {
    __shared__ float bs[G * G];
    __shared__ float srow[BG];
    __shared__ float swred[8];
    __shared__ float sv_s[BB];
    int tid = threadIdx.x;   // 256
    for (int i = tid; i < G * G; i += 256) bs[i] = bases[i];
    int b = tid >> 6, g = tid & 63;
    float bia = bias[g];
    float qv = g_qg[b][g];
    float m_run = -3.0e38f, den = 0.f, aggr = 0.f;
    __syncthreads();
    for (int n = blockIdx.x; n < NN; n += RB) {
        srow[tid] = g_sacc[n][tid];
        __syncthreads();
        float acc = bia;
        const float* sb = &srow[b * G];
        #pragma unroll 8
        for (int k = 0; k < G; k++) acc = fmaf(sb[k], bs[k * G + g], acc);
        acc = fmaxf(acc, 0.f);
        float p = acc * qv;
        p += __shfl_xor_sync(0xFFFFFFFFu, p, 16);
        p += __shfl_xor_sync(0xFFFFFFFFu, p, 8);
        p += __shfl_xor_sync(0xFFFFFFFFu, p, 4);
        p += __shfl_xor_sync(0xFFFFFFFFu, p, 2);
        p += __shfl_xor_sync(0xFFFFFFFFu, p, 1);
        if ((tid & 31) == 0) swred[tid >> 5] = p;
        __syncthreads();
        if (tid < BB) sv_s[tid] = swred[2 * tid] + swred[2 * tid + 1];
        __syncthreads();
        float sv = sv_s[b];
        float m_new = fmaxf(m_run, sv);
        float sc = __expf(m_run - m_new);
        float e = __expf(sv - m_new);
        aggr = aggr * sc + e * acc;
        den  = den * sc + e;
        m_run = m_new;
    }
    g_pagg[blockIdx.x][b][g] = aggr;
    if (g == 0) { g_pden[blockIdx.x][b] = den; g_pm[blockIdx.x][b] = m_run; }
}

// combine RB partial softmax blocks -> pooled feature. 1 block x 256.
__global__ void k_comb() {
    int tid = threadIdx.x;
    int b = tid >> 6, g = tid & 63;
    float m = -3.0e38f;
    #pragma unroll 4
    for (int i = 0; i < RB; i++) m = fmaxf(m, g_pm[i][b]);
    float acc = 0.f, den = 0.f;
    #pragma unroll 4
    for (int i = 0; i < RB; i++) {
        float sc = __expf(g_pm[i][b] - m);
        acc = fmaf(g_pagg[i][b][g], sc, acc);
        den = fmaf(g_pden[i][b], sc, den);
    }
    g_pool[b][g] = acc / den;
}

// hidden partials: 32 blocks = (hblk 0..7) x (kp 0..3); 128 threads
__global__ void k_hidden(const float* __restrict__ W1) {
    int hb = blockIdx.x >> 2, kp = blockIdx.x & 3;
    int tid = threadIdx.x;
    int h = hb * 128 + tid;
    int k0 = kp * 80;
    __shared__ float feat[BB][80];
    for (int i = tid; i < BB * 80; i += 128) {
        int b = i / 80, kk = i % 80, k = k0 + kk;
        feat[b][kk] = (k < G) ? g_pool[b][k] : g_qemb[b][k - G];
    }
    __syncthreads();
    float a0 = 0.f, a1 = 0.f, a2 = 0.f, a3 = 0.f;
    #pragma unroll 4
    for (int kk = 0; kk < 80; kk++) {
        float w = W1[(k0 + kk) * H1 + h];
        a0 = fmaf(feat[0][kk], w, a0);
        a1 = fmaf(feat[1][kk], w, a1);
        a2 = fmaf(feat[2][kk], w, a2);
        a3 = fmaf(feat[3][kk], w, a3);
    }
    g_hidp[kp][0][h] = a0; g_hidp[kp][1][h] = a1;
    g_hidp[kp][2][h] = a2; g_hidp[kp][3][h] = a3;
}

// logits: 63 blocks x 256 (8 k-parts x 32 classes); relu+bias fused.
__global__ void k_logits(const float* __restrict__ W2, const float* __restrict__ b1,
                         const float* __restrict__ b2, float* __restrict__ out) {
    __shared__ float hsm[BB][H1];
    __shared__ float red[8][32][BB];
    int tid = threadIdx.x;
    for (int i = tid; i < BB * H1; i += 256) {
        int b = i >> 10, k = i & (H1 - 1);
        float v = g_hidp[0][b][k] + g_hidp[1][b][k] + g_hidp[2][b][k] + g_hidp[3][b][k] + b1[k];
        hsm[b][k] = fmaxf(v, 0.f);
    }
    __syncthreads();
    int kp = tid >> 5, cl = tid & 31;
    int c = blockIdx.x * 32 + cl;
    float a0 = 0.f, a1 = 0.f, a2 = 0.f, a3 = 0.f;
    if (c < NC) {
        int k0 = kp * 128;
        #pragma unroll 4
        for (int k = k0; k < k0 + 128; k++) {
            float w = W2[k * NC + c];
            a0 = fmaf(hsm[0][k], w, a0);
            a1 = fmaf(hsm[1][k], w, a1);
            a2 = fmaf(hsm[2][k], w, a2);
            a3 = fmaf(hsm[3][k], w, a3);
        }
    }
    red[kp][cl][0] = a0; red[kp][cl][1] = a1; red[kp][cl][2] = a2; red[kp][cl][3] = a3;
    __syncthreads();
    if (kp == 0 && c < NC) {
        float bb2 = b2[c];
        #pragma unroll
        for (int b = 0; b < BB; b++) {
            float s = bb2;
            #pragma unroll
            for (int p = 0; p < 8; p++) s += red[p][cl][b];
            out[b * NC + c] = s;
        }
    }
}

// ---------------- launch ----------------
extern "C" void kernel_launch(void* const* d_in, const int* in_sizes, int n_in,
                              void* d_out, int out_size) {
    const int*   questions = (const int*)d_in[0];
    const int*   node_descs= (const int*)d_in[1];
    const int*   edge_src  = (const int*)d_in[2];
    const int*   edge_dst  = (const int*)d_in[3];
    const int*   edge_type = (const int*)d_in[4];
    const float* emb_word  = (const float*)d_in[5];
    const float* emb_desc  = (const float*)d_in[6];
    const float* Wx_f = (const float*)d_in[7];
    const float* Wh_f = (const float*)d_in[8];
    const float* bx_f = (const float*)d_in[9];
    const float* bh_f = (const float*)d_in[10];
    const float* Wx_b = (const float*)d_in[11];
    const float* Wh_b = (const float*)d_in[12];
    const float* bx_b = (const float*)d_in[13];
    const float* bh_b = (const float*)d_in[14];
    const float* W_hg = (const float*)d_in[15];
    const float* b_hg = (const float*)d_in[16];
    const float* bases = (const float*)d_in[17];
    const float* w_comp = (const float*)d_in[18];
    const float* rgcn_bias = (const float*)d_in[19];
    const float* W1 = (const float*)d_in[20];
    const float* b1 = (const float*)d_in[21];
    const float* W2 = (const float*)d_in[22];
    const float* b2 = (const float*)d_in[23];
    float* out = (float*)d_out;

    static cudaStream_t s1 = nullptr;
    static cudaEvent_t ev0 = nullptr, ev1 = nullptr;
    if (!s1) {
        cudaStreamCreateWithFlags(&s1, cudaStreamNonBlocking);
        cudaEventCreateWithFlags(&ev0, cudaEventDisableTiming);
        cudaEventCreateWithFlags(&ev1, cudaEventDisableTiming);
        cudaFuncSetAttribute(k_gru, cudaFuncAttributeMaxDynamicSharedMemorySize, SMEM_GRU);
    }

    cudaEventRecord(ev0, 0);
    cudaStreamWaitEvent(s1, ev0, 0);

    k_gx<<<64, G3>>>(questions, emb_word, Wx_f, bx_f, Wx_b, bx_b);        // 1
    k_gru<<<2, G3, SMEM_GRU>>>(questions, Wh_f, bh_f, Wh_b, bh_b);        // 2
    k_qg<<<1, 256>>>(W_hg, b_hg);                                          // 3
    k_nf0<<<NN / NFW, 256>>>(node_descs, emb_desc);                        // 4 (ncu slot)
    k_deg<<<(NE + 255) / 256, 256, 0, s1>>>(edge_dst);                     // 5 (overlaps)
    k_scan<<<1, 1024, 0, s1>>>();                                          // 6
    k_perm<<<(NE + 255) / 256, 256, 0, s1>>>(edge_src, edge_dst, edge_type, w_comp); // 7
    cudaEventRecord(ev1, s1);
    cudaStreamWaitEvent(0, ev1, 0);
    k_agg<<<(NN * 2 * 32 + 255) / 256, 256>>>();                           // 8
    k_rgcn<<<RB, 256>>>(bases, rgcn_bias);                                 // 9
    k_comb<<<1, 256>>>();                                                  // 10
    k_hidden<<<32, 128>>>(W1);                                             // 11
    k_logits<<<63, 256>>>(W2, b1, b2, out);                                // 12
}